// round 3
// baseline (speedup 1.0000x reference)
#include <cuda_runtime.h>

// ---------------- problem constants ----------------
#define BB 8
#define DD 512
#define T_TOT 36
#define DEMO_TT 4
#define OBS_TT 32
#define HWW 84
#define FF 128
#define NH 4
#define CH 32               // channels per head
#define DM (DEMO_TT*HWW)    // 336 demo positions
#define OM (OBS_TT*HWW)     // 2688 obs positions
#define CATP (DM+HWW)       // 420 concat positions
#define SPAT (T_TOT*HWW)    // 3024

static constexpr float INV_TEMP = 0.044194173824159216f; // 1/sqrt(512)

// ---------------- device scratch (no cudaMalloc allowed) ----------------
__device__ float g_x    [BB*DD*SPAT];    // running activation (B,512,36,84)
__device__ float g_dq   [BB*FF*DM];
__device__ float g_dk   [BB*FF*DM];
__device__ float g_dv   [BB*FF*DM];
__device__ float g_dvatt[BB*FF*DM];
__device__ float g_oq   [BB*FF*OM];
__device__ float g_ok   [BB*FF*OM];
__device__ float g_ov   [BB*FF*OM];
__device__ float g_pv   [BB*FF*OM];      // ov_att already in (n*32+c, t*84+i) layout

#define GBM 64
#define GBN 64
#define GBK 16

// ---------------- fused QKV GEMM ----------------
// Cq/Ck/Cv[z](FFxM) = Wq/Wk/Wv(FFxDD) * B[z](DDxM). B tile loaded once, reused 3x.
__global__ __launch_bounds__(256)
void gemm_qkv3(const float* __restrict__ Wq, const float* __restrict__ Wk,
               const float* __restrict__ Wv, const float* __restrict__ Bmat,
               float* __restrict__ Cq, float* __restrict__ Ck, float* __restrict__ Cv,
               int M, long long bStride, int ldb, long long cStride, int ldc)
{
    int z = blockIdx.z;
    const float* Bz = Bmat + (long long)z * bStride;
    int rowBase = blockIdx.x * GBM;
    int colBase = blockIdx.y * GBN;

    __shared__ float As[3][GBK][GBM+1];
    __shared__ float Bs[GBK][GBN+1];

    int tid = threadIdx.x;
    int tx = tid % 16, ty = tid / 16;
    float acc[3][4][4] = {};

    const float* W[3] = {Wq, Wk, Wv};

    for (int kt = 0; kt < DD; kt += GBK) {
        #pragma unroll
        for (int w = 0; w < 3; w++) {
            for (int l = tid; l < GBM*GBK; l += 256) {
                int m = l / GBK, k = l % GBK;
                As[w][k][m] = W[w][(long long)(rowBase + m)*DD + kt + k];
            }
        }
        for (int l = tid; l < GBK*GBN; l += 256) {
            int k = l / GBN, n = l % GBN;
            int gc = colBase + n;
            Bs[k][n] = (gc < M) ? Bz[(long long)(kt + k)*ldb + gc] : 0.f;
        }
        __syncthreads();
        #pragma unroll
        for (int k = 0; k < GBK; k++) {
            float bv[4];
            #pragma unroll
            for (int j = 0; j < 4; j++) bv[j] = Bs[k][tx*4 + j];
            #pragma unroll
            for (int w = 0; w < 3; w++) {
                float a[4];
                #pragma unroll
                for (int i = 0; i < 4; i++) a[i] = As[w][k][ty*4 + i];
                #pragma unroll
                for (int i = 0; i < 4; i++)
                    #pragma unroll
                    for (int j = 0; j < 4; j++)
                        acc[w][i][j] += a[i] * bv[j];
            }
        }
        __syncthreads();
    }
    float* C[3] = {Cq + (long long)z*cStride, Ck + (long long)z*cStride, Cv + (long long)z*cStride};
    #pragma unroll
    for (int w = 0; w < 3; w++) {
        #pragma unroll
        for (int i = 0; i < 4; i++) {
            int gr = rowBase + ty*4 + i;
            #pragma unroll
            for (int j = 0; j < 4; j++) {
                int gc = colBase + tx*4 + j;
                if (gc < M) C[w][(long long)gr*ldc + gc] = acc[w][i][j];
            }
        }
    }
}

// ---- output-projection GEMM with fused residual+relu epilogue into x ----
// A = wo (512x128), B = pv[b] (128x2688), x[b, gr, DM+gc] += relu(acc)
__global__ __launch_bounds__(256)
void gemm_wo(const float* __restrict__ A, const float* __restrict__ Bm,
             float* __restrict__ x)
{
    int b = blockIdx.z;
    Bm += (long long)b * FF * OM;
    int rowBase = blockIdx.x * GBM;
    int colBase = blockIdx.y * GBN;

    __shared__ float As[GBK][GBM+1];
    __shared__ float Bs[GBK][GBN+1];

    int tid = threadIdx.x;
    int tx = tid % 16, ty = tid / 16;
    float acc[4][4] = {};

    for (int kt = 0; kt < FF; kt += GBK) {
        for (int l = tid; l < GBM*GBK; l += 256) {
            int m = l / GBK, k = l % GBK;
            As[k][m] = A[(long long)(rowBase + m)*FF + kt + k];
        }
        for (int l = tid; l < GBK*GBN; l += 256) {
            int k = l / GBN, n = l % GBN;
            int gc = colBase + n;
            Bs[k][n] = (gc < OM) ? Bm[(long long)(kt + k)*OM + gc] : 0.f;
        }
        __syncthreads();
        #pragma unroll
        for (int k = 0; k < GBK; k++) {
            float a[4], bv[4];
            #pragma unroll
            for (int i = 0; i < 4; i++) a[i]  = As[k][ty*4 + i];
            #pragma unroll
            for (int j = 0; j < 4; j++) bv[j] = Bs[k][tx*4 + j];
            #pragma unroll
            for (int i = 0; i < 4; i++)
                #pragma unroll
                for (int j = 0; j < 4; j++)
                    acc[i][j] += a[i] * bv[j];
        }
        __syncthreads();
    }
    #pragma unroll
    for (int i = 0; i < 4; i++) {
        int gr = rowBase + ty*4 + i;
        #pragma unroll
        for (int j = 0; j < 4; j++) {
            int gc = colBase + tx*4 + j;
            if (gc < OM) {
                long long xi = ((long long)(b*DD + gr))*SPAT + DM + gc;
                x[xi] += fmaxf(acc[i][j], 0.f);
            }
        }
    }
}

// ---------------- fused demo attention + dv_att ----------------
// block per (b,n,i): logits over j (causal block mask), softmax, and
// dvatt[c,i] = sum_j dv[c,j] * probs[j] computed in-block.
__global__ void demo_attn_kernel(const float* __restrict__ dk,
                                 const float* __restrict__ dq,
                                 const float* __restrict__ dv,
                                 float* __restrict__ dvatt)
{
    int i = blockIdx.x;      // 0..335
    int n = blockIdx.y;      // head
    int b = blockIdx.z;
    const long long base = ((long long)b*FF + n*CH) * DM;
    const float* Kp = dk + base;
    const float* Qp = dq + base;
    const float* Vp = dv + base;

    __shared__ float kv[CH];
    __shared__ float logit[DM];
    __shared__ float red[128];
    __shared__ float part[CH*128];
    int tid = threadIdx.x;

    if (tid < CH) kv[tid] = Kp[tid*DM + i];
    __syncthreads();

    int nvalid = (i / HWW + 1) * HWW;   // causal block mask: j valid iff t_j <= t_i

    float lmax = -1e30f;
    for (int j = tid; j < nvalid; j += 128) {
        float s = 0.f;
        #pragma unroll
        for (int c = 0; c < CH; c++) s += kv[c] * Qp[c*DM + j];
        s *= INV_TEMP;
        logit[j] = s;
        lmax = fmaxf(lmax, s);
    }
    red[tid] = lmax; __syncthreads();
    for (int o = 64; o > 0; o >>= 1) { if (tid < o) red[tid] = fmaxf(red[tid], red[tid+o]); __syncthreads(); }
    float m = red[0];
    __syncthreads();

    float lsum = 0.f;
    for (int j = tid; j < nvalid; j += 128) {
        float e = __expf(logit[j] - m);
        logit[j] = e;
        lsum += e;
    }
    red[tid] = lsum; __syncthreads();
    for (int o = 64; o > 0; o >>= 1) { if (tid < o) red[tid] += red[tid+o]; __syncthreads(); }
    float inv = 1.f / red[0];
    __syncthreads();

    // epilogue: acc[c] = sum_j e[j] * dv[c,j]  (coalesced over j)
    float acc[CH] = {};
    for (int j = tid; j < nvalid; j += 128) {
        float p = logit[j];
        #pragma unroll
        for (int c = 0; c < CH; c++) acc[c] += p * Vp[c*DM + j];
    }
    #pragma unroll
    for (int c = 0; c < CH; c++) part[c*128 + tid] = acc[c];
    __syncthreads();
    for (int o = 64; o > 0; o >>= 1) {
        for (int idx = tid; idx < CH*o; idx += 128) {
            int c = idx / o, t = idx % o;
            part[c*128 + t] += part[c*128 + t + o];
        }
        __syncthreads();
    }
    if (tid < CH) dvatt[base + tid*DM + i] = part[tid*128] * inv;
}

// ---------------- fused obs attention per (b,t,n) ----------------
// cat_k/cat_v = [demo (336) | obs (84)] along p; S[p][j] = cat_k[:,p].oq[:,j]/T;
// softmax over j per p; out[c][i] = sum_p cat_v[c,p]*attn[p,i]; written in wo-input layout.
#define PCH 64
__global__ void obs_attn_kernel(const float* __restrict__ dk,
                                const float* __restrict__ dvatt,
                                const float* __restrict__ ok,
                                const float* __restrict__ ov,
                                const float* __restrict__ oq,
                                float* __restrict__ pv)
{
    int n = blockIdx.x, t = blockIdx.y, b = blockIdx.z;
    const long long obase = ((long long)b*FF + n*CH) * OM + (long long)t*HWW;
    const long long dbase = ((long long)b*FF + n*CH) * DM;

    __shared__ float qs[CH][HWW];     // 32x84
    __shared__ float ks[CH][PCH];     // 32x64
    __shared__ float vs[CH][PCH];
    __shared__ float S[PCH][HWW+1];   // 64x85

    int tid = threadIdx.x;
    int tx = tid % 16, ty = tid / 16;

    for (int l = tid; l < CH*HWW; l += 256) {
        int c = l / HWW, j = l % HWW;
        qs[c][j] = oq[obase + (long long)c*OM + j];
    }

    float acc[2][6] = {};

    for (int p0 = 0; p0 < CATP; p0 += PCH) {
        // load K/V chunk
        for (int l = tid; l < CH*PCH; l += 256) {
            int c = l / PCH, pl = l % PCH;
            int p = p0 + pl;
            float kk = 0.f, vv = 0.f;
            if (p < DM) {
                kk = dk   [dbase + (long long)c*DM + p];
                vv = dvatt[dbase + (long long)c*DM + p];
            } else if (p < CATP) {
                kk = ok[obase + (long long)c*OM + (p - DM)];
                vv = ov[obase + (long long)c*OM + (p - DM)];
            }
            ks[c][pl] = kk; vs[c][pl] = vv;
        }
        __syncthreads();

        // logits: rows p = ty*4+pp, cols j = tx*6+jj
        {
            float sa[4][6] = {};
            #pragma unroll
            for (int k = 0; k < CH; k++) {
                float a[4], bq[6];
                #pragma unroll
                for (int pp = 0; pp < 4; pp++) a[pp] = ks[k][ty*4 + pp];
                #pragma unroll
                for (int jj = 0; jj < 6; jj++) {
                    int j = tx*6 + jj;
                    bq[jj] = (j < HWW) ? qs[k][j] : 0.f;
                }
                #pragma unroll
                for (int pp = 0; pp < 4; pp++)
                    #pragma unroll
                    for (int jj = 0; jj < 6; jj++)
                        sa[pp][jj] += a[pp] * bq[jj];
            }
            #pragma unroll
            for (int pp = 0; pp < 4; pp++)
                #pragma unroll
                for (int jj = 0; jj < 6; jj++) {
                    int j = tx*6 + jj;
                    if (j < HWW) S[ty*4 + pp][j] = sa[pp][jj] * INV_TEMP;
                }
        }
        __syncthreads();

        // per-row softmax over the 84 axis
        if (tid < PCH) {
            int p = p0 + tid;
            if (p < CATP) {
                float mx = -1e30f;
                for (int j = 0; j < HWW; j++) mx = fmaxf(mx, S[tid][j]);
                float sum = 0.f;
                for (int j = 0; j < HWW; j++) { float e = __expf(S[tid][j] - mx); S[tid][j] = e; sum += e; }
                float iv = 1.f / sum;
                for (int j = 0; j < HWW; j++) S[tid][j] *= iv;
            } else {
                for (int j = 0; j < HWW; j++) S[tid][j] = 0.f;
            }
        }
        __syncthreads();

        // accumulate V @ attn : c = ty (+16), i = tx*6+jj
        #pragma unroll 4
        for (int pl = 0; pl < PCH; pl++) {
            float v0 = vs[ty][pl];
            float v1 = vs[ty+16][pl];
            float sv[6];
            #pragma unroll
            for (int jj = 0; jj < 6; jj++) {
                int i = tx*6 + jj;
                sv[jj] = (i < HWW) ? S[pl][i] : 0.f;
            }
            #pragma unroll
            for (int jj = 0; jj < 6; jj++) {
                acc[0][jj] += v0 * sv[jj];
                acc[1][jj] += v1 * sv[jj];
            }
        }
        __syncthreads();
    }

    #pragma unroll
    for (int cc = 0; cc < 2; cc++) {
        int c = ty + 16*cc;
        #pragma unroll
        for (int jj = 0; jj < 6; jj++) {
            int i = tx*6 + jj;
            if (i < HWW) pv[obase + (long long)c*OM + i] = acc[cc][jj];
        }
    }
}

// ---------------- batchnorm over (B, T, H, W) per channel ----------------
__global__ void bn_kernel(const float* __restrict__ x, float* __restrict__ out,
                          const float* __restrict__ gamma, const float* __restrict__ beta)
{
    int ch = blockIdx.x;
    int tid = threadIdx.x;
    const long long chOff = (long long)ch * SPAT;

    double s = 0.0, s2 = 0.0;
    for (int b = 0; b < BB; b++) {
        const float* p = x + (long long)b*DD*SPAT + chOff;
        for (int idx = tid; idx < SPAT; idx += 256) {
            float v = p[idx];
            s  += v;
            s2 += (double)v * v;
        }
    }
    __shared__ double rs[256], rs2[256];
    rs[tid] = s; rs2[tid] = s2; __syncthreads();
    for (int o = 128; o > 0; o >>= 1) {
        if (tid < o) { rs[tid] += rs[tid+o]; rs2[tid] += rs2[tid+o]; }
        __syncthreads();
    }
    const double cnt = (double)BB * SPAT;
    double mean = rs[0] / cnt;
    double var  = rs2[0] / cnt - mean*mean;
    float scale = (float)((double)gamma[ch] * rsqrt(var + 1e-5));
    float mn = (float)mean;
    float bt = beta[ch];
    for (int b = 0; b < BB; b++) {
        const float* p = x   + (long long)b*DD*SPAT + chOff;
        float*       q = out + (long long)b*DD*SPAT + chOff;
        for (int idx = tid; idx < SPAT; idx += 256)
            q[idx] = scale * (p[idx] - mn) + bt;
    }
}

// ---------------- host driver ----------------
extern "C" void kernel_launch(void* const* d_in, const int* in_sizes, int n_in,
                              void* d_out, int out_size)
{
    const float* inputs  = (const float*)d_in[0];
    const float* demo_wq = (const float*)d_in[1];
    const float* demo_wk = (const float*)d_in[2];
    const float* demo_wv = (const float*)d_in[3];
    // demo_wo (d_in[4]) is unused by the reference
    const float* obs_wq  = (const float*)d_in[5];
    const float* obs_wk  = (const float*)d_in[6];
    const float* obs_wv  = (const float*)d_in[7];
    const float* obs_wo  = (const float*)d_in[8];
    const float* bn_g    = (const float*)d_in[9];
    const float* bn_b    = (const float*)d_in[10];
    float* out = (float*)d_out;

    float *xp, *dqp, *dkp, *dvp, *dvattp, *oqp, *okp, *ovp, *pvp;
    cudaGetSymbolAddress((void**)&xp,     g_x);
    cudaGetSymbolAddress((void**)&dqp,    g_dq);
    cudaGetSymbolAddress((void**)&dkp,    g_dk);
    cudaGetSymbolAddress((void**)&dvp,    g_dv);
    cudaGetSymbolAddress((void**)&dvattp, g_dvatt);
    cudaGetSymbolAddress((void**)&oqp,    g_oq);
    cudaGetSymbolAddress((void**)&okp,    g_ok);
    cudaGetSymbolAddress((void**)&ovp,    g_ov);
    cudaGetSymbolAddress((void**)&pvp,    g_pv);

    cudaMemcpyAsync(xp, inputs, (size_t)BB*DD*SPAT*sizeof(float),
                    cudaMemcpyDeviceToDevice, 0);

    const long long XB = (long long)DD * SPAT;    // batch stride of x
    const long long QD = (long long)FF * DM;      // batch stride of demo qkv
    const long long QO = (long long)FF * OM;      // batch stride of obs qkv

    for (int i = 0; i < 2; i++) {
        const float* dwq = demo_wq + (long long)i*FF*DD;
        const float* dwk = demo_wk + (long long)i*FF*DD;
        const float* dwv = demo_wv + (long long)i*FF*DD;
        const float* owq = obs_wq  + (long long)i*FF*DD;
        const float* owk = obs_wk  + (long long)i*FF*DD;
        const float* owv = obs_wv  + (long long)i*FF*DD;
        const float* wo  = obs_wo  + (long long)i*DD*FF;

        // demo QKV: (128x512) x (512x336) per batch, q/k/v fused
        gemm_qkv3<<<dim3(2, 6, BB), 256>>>(dwq, dwk, dwv, xp,
                                           dqp, dkp, dvp, DM, XB, SPAT, QD, DM);

        // fused demo attention + dv_att
        demo_attn_kernel<<<dim3(DM, NH, BB), 128>>>(dkp, dqp, dvp, dvattp);

        // obs QKV: (128x512) x (512x2688) per batch, q/k/v fused
        gemm_qkv3<<<dim3(2, 42, BB), 256>>>(owq, owk, owv, xp + DM,
                                            oqp, okp, ovp, OM, XB, SPAT, QO, OM);

        // fused obs attention
        obs_attn_kernel<<<dim3(NH, OBS_TT, BB), 256>>>(dkp, dvattp, okp, ovp, oqp, pvp);

        // output projection + residual + relu, fused into x
        gemm_wo<<<dim3(8, 42, BB), 256>>>(wo, pvp, xp);

        // batchnorm (last layer writes final output)
        bn_kernel<<<DD, 256>>>(xp, (i == 1) ? out : xp, bn_g + i*DD, bn_b + i*DD);
    }
}

// round 4
// speedup vs baseline: 1.5272x; 1.5272x over previous
#include <cuda_runtime.h>

// ---------------- problem constants ----------------
#define BB 8
#define DD 512
#define T_TOT 36
#define DEMO_TT 4
#define OBS_TT 32
#define HWW 84
#define FF 128
#define NH 4
#define CH 32               // channels per head
#define DM (DEMO_TT*HWW)    // 336 demo positions
#define OM (OBS_TT*HWW)     // 2688 obs positions
#define CATP (DM+HWW)       // 420 concat positions
#define SPAT (T_TOT*HWW)    // 3024

static constexpr float INV_TEMP = 0.044194173824159216f; // 1/sqrt(512)

// ---------------- device scratch (no cudaMalloc allowed) ----------------
__device__ float g_x    [BB*DD*SPAT];    // running activation (B,512,36,84)
__device__ float g_dq   [BB*FF*DM];
__device__ float g_dk   [BB*FF*DM];
__device__ float g_dv   [BB*FF*DM];
__device__ float g_dvatt[BB*FF*DM];
__device__ float g_oq   [BB*FF*OM];
__device__ float g_ok   [BB*FF*OM];
__device__ float g_ov   [BB*FF*OM];
__device__ float g_pv   [BB*FF*OM];      // ov_att already in (n*32+c, t*84+i) layout

// ================= high-throughput GEMM building block =================
// 128x128 tile, 8x8 microtile, 256 threads, BK=16, float4 everywhere.
#define BM 128
#define BN 128
#define BKK 16

// ---------------- fused QKV GEMM ----------------
// blockIdx.x selects W in {q,k,v}; C_w[z](FFxM) = W(FFx512) * B[z](512xM)
__global__ __launch_bounds__(256)
void gemm_qkv(const float* __restrict__ Wq, const float* __restrict__ Wk,
              const float* __restrict__ Wv, const float* __restrict__ Bmat,
              float* __restrict__ Cq, float* __restrict__ Ck, float* __restrict__ Cv,
              int M, long long bStride, int ldb, long long cStride, int ldc)
{
    int w = blockIdx.x;
    const float* W = (w == 0) ? Wq : (w == 1) ? Wk : Wv;
    float* Cc = ((w == 0) ? Cq : (w == 1) ? Ck : Cv) + (long long)blockIdx.z * cStride;
    const float* Bz = Bmat + (long long)blockIdx.z * bStride;
    int colBase = blockIdx.y * BN;
    bool fullTile = (colBase + BN <= M);

    __shared__ float As[BKK][BM];
    __shared__ float Bs[BKK][BN];

    int tid = threadIdx.x;
    int tx = tid % 16, ty = tid / 16;
    float acc[8][8] = {};

    for (int kt = 0; kt < DD; kt += BKK) {
        // A: 128 rows x 16 k = 512 float4, 2 per thread; transpose into As[k][m]
        #pragma unroll
        for (int r = 0; r < 2; r++) {
            int f = tid + r*256;
            int m = f >> 2;
            int k0 = (f & 3) * 4;
            float4 v = *(const float4*)&W[(long long)m*DD + kt + k0];
            As[k0+0][m] = v.x; As[k0+1][m] = v.y; As[k0+2][m] = v.z; As[k0+3][m] = v.w;
        }
        // B: 16 k x 128 n = 512 float4, 2 per thread
        #pragma unroll
        for (int r = 0; r < 2; r++) {
            int f = tid + r*256;
            int k = f >> 5;
            int n4 = (f & 31) * 4;
            int gc = colBase + n4;
            const float* src = &Bz[(long long)(kt + k)*ldb + gc];
            if (fullTile) {
                *(float4*)&Bs[k][n4] = *(const float4*)src;
            } else {
                float4 v;
                v.x = (gc+0 < M) ? src[0] : 0.f;
                v.y = (gc+1 < M) ? src[1] : 0.f;
                v.z = (gc+2 < M) ? src[2] : 0.f;
                v.w = (gc+3 < M) ? src[3] : 0.f;
                *(float4*)&Bs[k][n4] = v;
            }
        }
        __syncthreads();
        #pragma unroll
        for (int k = 0; k < BKK; k++) {
            float a[8], b[8];
            *(float4*)&a[0] = *(float4*)&As[k][ty*8];
            *(float4*)&a[4] = *(float4*)&As[k][ty*8 + 4];
            *(float4*)&b[0] = *(float4*)&Bs[k][tx*8];
            *(float4*)&b[4] = *(float4*)&Bs[k][tx*8 + 4];
            #pragma unroll
            for (int i = 0; i < 8; i++)
                #pragma unroll
                for (int j = 0; j < 8; j++)
                    acc[i][j] += a[i] * b[j];
        }
        __syncthreads();
    }
    #pragma unroll
    for (int i = 0; i < 8; i++) {
        int gr = ty*8 + i;
        #pragma unroll
        for (int j = 0; j < 8; j += 4) {
            int gc = colBase + tx*8 + j;
            if (fullTile) {
                *(float4*)&Cc[(long long)gr*ldc + gc] =
                    make_float4(acc[i][j], acc[i][j+1], acc[i][j+2], acc[i][j+3]);
            } else {
                #pragma unroll
                for (int q = 0; q < 4; q++)
                    if (gc + q < M) Cc[(long long)gr*ldc + gc + q] = acc[i][j+q];
            }
        }
    }
}

// ---- output-projection GEMM (512x2688 = 512x128 * 128x2688) with fused residual+relu ----
__global__ __launch_bounds__(256)
void gemm_wo(const float* __restrict__ A, const float* __restrict__ Bm,
             float* __restrict__ x)
{
    int b = blockIdx.z;
    Bm += (long long)b * FF * OM;
    int rowBase = blockIdx.x * BM;
    int colBase = blockIdx.y * BN;

    __shared__ float As[BKK][BM];
    __shared__ float Bs[BKK][BN];

    int tid = threadIdx.x;
    int tx = tid % 16, ty = tid / 16;
    float acc[8][8] = {};

    for (int kt = 0; kt < FF; kt += BKK) {
        #pragma unroll
        for (int r = 0; r < 2; r++) {
            int f = tid + r*256;
            int m = f >> 2;
            int k0 = (f & 3) * 4;
            float4 v = *(const float4*)&A[(long long)(rowBase + m)*FF + kt + k0];
            As[k0+0][m] = v.x; As[k0+1][m] = v.y; As[k0+2][m] = v.z; As[k0+3][m] = v.w;
        }
        #pragma unroll
        for (int r = 0; r < 2; r++) {
            int f = tid + r*256;
            int k = f >> 5;
            int n4 = (f & 31) * 4;
            *(float4*)&Bs[k][n4] = *(const float4*)&Bm[(long long)(kt + k)*OM + colBase + n4];
        }
        __syncthreads();
        #pragma unroll
        for (int k = 0; k < BKK; k++) {
            float a[8], bv[8];
            *(float4*)&a[0]  = *(float4*)&As[k][ty*8];
            *(float4*)&a[4]  = *(float4*)&As[k][ty*8 + 4];
            *(float4*)&bv[0] = *(float4*)&Bs[k][tx*8];
            *(float4*)&bv[4] = *(float4*)&Bs[k][tx*8 + 4];
            #pragma unroll
            for (int i = 0; i < 8; i++)
                #pragma unroll
                for (int j = 0; j < 8; j++)
                    acc[i][j] += a[i] * bv[j];
        }
        __syncthreads();
    }
    #pragma unroll
    for (int i = 0; i < 8; i++) {
        int gr = rowBase + ty*8 + i;
        long long xrow = ((long long)(b*DD + gr))*SPAT + DM;
        #pragma unroll
        for (int j = 0; j < 8; j++) {
            int gc = colBase + tx*8 + j;
            x[xrow + gc] += fmaxf(acc[i][j], 0.f);
        }
    }
}

// ---------------- fused demo attention + dv_att ----------------
__global__ void demo_attn_kernel(const float* __restrict__ dk,
                                 const float* __restrict__ dq,
                                 const float* __restrict__ dv,
                                 float* __restrict__ dvatt)
{
    int i = blockIdx.x;      // 0..335
    int n = blockIdx.y;      // head
    int b = blockIdx.z;
    const long long base = ((long long)b*FF + n*CH) * DM;
    const float* Kp = dk + base;
    const float* Qp = dq + base;
    const float* Vp = dv + base;

    __shared__ float kv[CH];
    __shared__ float logit[DM];
    __shared__ float red[128];
    __shared__ float part[CH*128];
    int tid = threadIdx.x;

    if (tid < CH) kv[tid] = Kp[tid*DM + i];
    __syncthreads();

    int nvalid = (i / HWW + 1) * HWW;   // causal block mask

    float lmax = -1e30f;
    for (int j = tid; j < nvalid; j += 128) {
        float s = 0.f;
        #pragma unroll
        for (int c = 0; c < CH; c++) s += kv[c] * Qp[c*DM + j];
        s *= INV_TEMP;
        logit[j] = s;
        lmax = fmaxf(lmax, s);
    }
    red[tid] = lmax; __syncthreads();
    for (int o = 64; o > 0; o >>= 1) { if (tid < o) red[tid] = fmaxf(red[tid], red[tid+o]); __syncthreads(); }
    float m = red[0];
    __syncthreads();

    float lsum = 0.f;
    for (int j = tid; j < nvalid; j += 128) {
        float e = __expf(logit[j] - m);
        logit[j] = e;
        lsum += e;
    }
    red[tid] = lsum; __syncthreads();
    for (int o = 64; o > 0; o >>= 1) { if (tid < o) red[tid] += red[tid+o]; __syncthreads(); }
    float inv = 1.f / red[0];
    __syncthreads();

    float acc[CH] = {};
    for (int j = tid; j < nvalid; j += 128) {
        float p = logit[j];
        #pragma unroll
        for (int c = 0; c < CH; c++) acc[c] += p * Vp[c*DM + j];
    }
    #pragma unroll
    for (int c = 0; c < CH; c++) part[c*128 + tid] = acc[c];
    __syncthreads();
    for (int o = 64; o > 0; o >>= 1) {
        for (int idx = tid; idx < CH*o; idx += 128) {
            int c = idx / o, t = idx % o;
            part[c*128 + t] += part[c*128 + t + o];
        }
        __syncthreads();
    }
    if (tid < CH) dvatt[base + tid*DM + i] = part[tid*128] * inv;
}

// ---------------- fused obs attention per (b,t,n) ----------------
#define PCH 64
__global__ void obs_attn_kernel(const float* __restrict__ dk,
                                const float* __restrict__ dvatt,
                                const float* __restrict__ ok,
                                const float* __restrict__ ov,
                                const float* __restrict__ oq,
                                float* __restrict__ pv)
{
    int n = blockIdx.x, t = blockIdx.y, b = blockIdx.z;
    const long long obase = ((long long)b*FF + n*CH) * OM + (long long)t*HWW;
    const long long dbase = ((long long)b*FF + n*CH) * DM;

    __shared__ float qs[CH][HWW];     // 32x84
    __shared__ float ks[CH][PCH];     // 32x64
    __shared__ float vs[CH][PCH];
    __shared__ float S[PCH][HWW+1];   // 64x85

    int tid = threadIdx.x;
    int tx = tid % 16, ty = tid / 16;

    for (int l = tid; l < CH*HWW; l += 256) {
        int c = l / HWW, j = l % HWW;
        qs[c][j] = oq[obase + (long long)c*OM + j];
    }

    float acc[2][6] = {};

    for (int p0 = 0; p0 < CATP; p0 += PCH) {
        // load K/V chunk
        for (int l = tid; l < CH*PCH; l += 256) {
            int c = l / PCH, pl = l % PCH;
            int p = p0 + pl;
            float kk = 0.f, vv = 0.f;
            if (p < DM) {
                kk = dk   [dbase + (long long)c*DM + p];
                vv = dvatt[dbase + (long long)c*DM + p];
            } else if (p < CATP) {
                kk = ok[obase + (long long)c*OM + (p - DM)];
                vv = ov[obase + (long long)c*OM + (p - DM)];
            }
            ks[c][pl] = kk; vs[c][pl] = vv;
        }
        __syncthreads();

        // logits
        {
            float sa[4][6] = {};
            #pragma unroll
            for (int k = 0; k < CH; k++) {
                float a[4], bq[6];
                #pragma unroll
                for (int pp = 0; pp < 4; pp++) a[pp] = ks[k][ty*4 + pp];
                #pragma unroll
                for (int jj = 0; jj < 6; jj++) {
                    int j = tx*6 + jj;
                    bq[jj] = (j < HWW) ? qs[k][j] : 0.f;
                }
                #pragma unroll
                for (int pp = 0; pp < 4; pp++)
                    #pragma unroll
                    for (int jj = 0; jj < 6; jj++)
                        sa[pp][jj] += a[pp] * bq[jj];
            }
            #pragma unroll
            for (int pp = 0; pp < 4; pp++)
                #pragma unroll
                for (int jj = 0; jj < 6; jj++) {
                    int j = tx*6 + jj;
                    if (j < HWW) S[ty*4 + pp][j] = sa[pp][jj] * INV_TEMP;
                }
        }
        __syncthreads();

        // parallel softmax: 4 threads per row, shfl reductions in the 4-group
        {
            int row = tid >> 2;     // 0..63
            int l4  = tid & 3;
            float mx = -1e30f;
            for (int j = l4; j < HWW; j += 4) mx = fmaxf(mx, S[row][j]);
            mx = fmaxf(mx, __shfl_xor_sync(0xffffffffu, mx, 1));
            mx = fmaxf(mx, __shfl_xor_sync(0xffffffffu, mx, 2));
            float sum = 0.f;
            for (int j = l4; j < HWW; j += 4) {
                float e = __expf(S[row][j] - mx);
                S[row][j] = e;
                sum += e;
            }
            sum += __shfl_xor_sync(0xffffffffu, sum, 1);
            sum += __shfl_xor_sync(0xffffffffu, sum, 2);
            float iv = 1.f / sum;
            bool valid = (p0 + row) < CATP;
            for (int j = l4; j < HWW; j += 4)
                S[row][j] = valid ? S[row][j] * iv : 0.f;
        }
        __syncthreads();

        // accumulate V @ attn : c = ty (+16), i = tx*6+jj
        #pragma unroll 4
        for (int pl = 0; pl < PCH; pl++) {
            float v0 = vs[ty][pl];
            float v1 = vs[ty+16][pl];
            float sv[6];
            #pragma unroll
            for (int jj = 0; jj < 6; jj++) {
                int i = tx*6 + jj;
                sv[jj] = (i < HWW) ? S[pl][i] : 0.f;
            }
            #pragma unroll
            for (int jj = 0; jj < 6; jj++) {
                acc[0][jj] += v0 * sv[jj];
                acc[1][jj] += v1 * sv[jj];
            }
        }
        __syncthreads();
    }

    #pragma unroll
    for (int cc = 0; cc < 2; cc++) {
        int c = ty + 16*cc;
        #pragma unroll
        for (int jj = 0; jj < 6; jj++) {
            int i = tx*6 + jj;
            if (i < HWW) pv[obase + (long long)c*OM + i] = acc[cc][jj];
        }
    }
}

// ---------------- batchnorm over (B, T, H, W) per channel ----------------
__global__ void bn_kernel(const float* __restrict__ x, float* __restrict__ out,
                          const float* __restrict__ gamma, const float* __restrict__ beta)
{
    int ch = blockIdx.x;
    int tid = threadIdx.x;
    const long long chOff = (long long)ch * SPAT;

    double s = 0.0, s2 = 0.0;
    for (int b = 0; b < BB; b++) {
        const float* p = x + (long long)b*DD*SPAT + chOff;
        for (int idx = tid; idx < SPAT; idx += 256) {
            float v = p[idx];
            s  += v;
            s2 += (double)v * v;
        }
    }
    __shared__ double rs[256], rs2[256];
    rs[tid] = s; rs2[tid] = s2; __syncthreads();
    for (int o = 128; o > 0; o >>= 1) {
        if (tid < o) { rs[tid] += rs[tid+o]; rs2[tid] += rs2[tid+o]; }
        __syncthreads();
    }
    const double cnt = (double)BB * SPAT;
    double mean = rs[0] / cnt;
    double var  = rs2[0] / cnt - mean*mean;
    float scale = (float)((double)gamma[ch] * rsqrt(var + 1e-5));
    float mn = (float)mean;
    float bt = beta[ch];
    for (int b = 0; b < BB; b++) {
        const float* p = x   + (long long)b*DD*SPAT + chOff;
        float*       q = out + (long long)b*DD*SPAT + chOff;
        for (int idx = tid; idx < SPAT; idx += 256)
            q[idx] = scale * (p[idx] - mn) + bt;
    }
}

// ---------------- host driver ----------------
extern "C" void kernel_launch(void* const* d_in, const int* in_sizes, int n_in,
                              void* d_out, int out_size)
{
    const float* inputs  = (const float*)d_in[0];
    const float* demo_wq = (const float*)d_in[1];
    const float* demo_wk = (const float*)d_in[2];
    const float* demo_wv = (const float*)d_in[3];
    // demo_wo (d_in[4]) is unused by the reference
    const float* obs_wq  = (const float*)d_in[5];
    const float* obs_wk  = (const float*)d_in[6];
    const float* obs_wv  = (const float*)d_in[7];
    const float* obs_wo  = (const float*)d_in[8];
    const float* bn_g    = (const float*)d_in[9];
    const float* bn_b    = (const float*)d_in[10];
    float* out = (float*)d_out;

    float *xp, *dqp, *dkp, *dvp, *dvattp, *oqp, *okp, *ovp, *pvp;
    cudaGetSymbolAddress((void**)&xp,     g_x);
    cudaGetSymbolAddress((void**)&dqp,    g_dq);
    cudaGetSymbolAddress((void**)&dkp,    g_dk);
    cudaGetSymbolAddress((void**)&dvp,    g_dv);
    cudaGetSymbolAddress((void**)&dvattp, g_dvatt);
    cudaGetSymbolAddress((void**)&oqp,    g_oq);
    cudaGetSymbolAddress((void**)&okp,    g_ok);
    cudaGetSymbolAddress((void**)&ovp,    g_ov);
    cudaGetSymbolAddress((void**)&pvp,    g_pv);

    cudaMemcpyAsync(xp, inputs, (size_t)BB*DD*SPAT*sizeof(float),
                    cudaMemcpyDeviceToDevice, 0);

    const long long XB = (long long)DD * SPAT;    // batch stride of x
    const long long QD = (long long)FF * DM;      // batch stride of demo qkv
    const long long QO = (long long)FF * OM;      // batch stride of obs qkv

    for (int i = 0; i < 2; i++) {
        const float* dwq = demo_wq + (long long)i*FF*DD;
        const float* dwk = demo_wk + (long long)i*FF*DD;
        const float* dwv = demo_wv + (long long)i*FF*DD;
        const float* owq = obs_wq  + (long long)i*FF*DD;
        const float* owk = obs_wk  + (long long)i*FF*DD;
        const float* owv = obs_wv  + (long long)i*FF*DD;
        const float* wo  = obs_wo  + (long long)i*DD*FF;

        // demo QKV: 3 x (128x512)x(512x336), per batch
        gemm_qkv<<<dim3(3, (DM + BN - 1)/BN, BB), 256>>>(dwq, dwk, dwv, xp,
                                                         dqp, dkp, dvp, DM, XB, SPAT, QD, DM);

        // fused demo attention + dv_att
        demo_attn_kernel<<<dim3(DM, NH, BB), 128>>>(dkp, dqp, dvp, dvattp);

        // obs QKV: 3 x (128x512)x(512x2688), per batch
        gemm_qkv<<<dim3(3, OM/BN, BB), 256>>>(owq, owk, owv, xp + DM,
                                              oqp, okp, ovp, OM, XB, SPAT, QO, OM);

        // fused obs attention
        obs_attn_kernel<<<dim3(NH, OBS_TT, BB), 256>>>(dkp, dvattp, okp, ovp, oqp, pvp);

        // output projection + residual + relu, fused into x
        gemm_wo<<<dim3(DD/BM, OM/BN, BB), 256>>>(wo, pvp, xp);

        // batchnorm (last layer writes final output)
        bn_kernel<<<DD, 256>>>(xp, (i == 1) ? out : xp, bn_g + i*DD, bn_b + i*DD);
    }
}